// round 11
// baseline (speedup 1.0000x reference)
#include <cuda_runtime.h>

#define G_SEG   20000
#define M_MEM   5120000
#define D_FEAT  256
#define R_REP   2

#define MEMBER_BLOCKS 5000            // (M/4)/256
#define GEMV_BLOCKS   2500            // 20000 warps / 8 warps per block
#define TOTAL_BLOCKS  (MEMBER_BLOCKS + GEMV_BLOCKS)
#define FIN_BLOCKS    64
#define FIN_THREADS   (FIN_BLOCKS * 256)

// Replicated per-glimpse accumulators: {sum_e, sum_e*px, sum_e*py, sum_e*pz}.
// 2 * 20000 * 16B = 640 KB, L2-resident. Zero-initialized at module load;
// the tail finalize re-zeroes after reading, so every graph replay starts clean.
__device__ float4 g_acc[R_REP][G_SEG];

// Completion counters (zero-initialized; last tail block resets both).
__device__ unsigned int g_done;
__device__ unsigned int g_fin;

// One vectorized reduction per member: red.global.add.v4.f32 (sm_90+).
__device__ __forceinline__ void red_v4(float4* p, float a, float b, float c, float d) {
    asm volatile("red.global.add.v4.f32 [%0], {%1, %2, %3, %4};"
                 :: "l"(p), "f"(a), "f"(b), "f"(c), "f"(d)
                 : "memory");
}

// Fused kernel, 2:1 interleaved roles (R9 core — best measured):
//   blockIdx % 3 != 2 -> member scatter-reduce (4 members/thread)
//   blockIdx % 3 == 2 -> GEMV + presence logits (DRAM-streaming)
// Tail: last FIN_BLOCKS finishers run the center finalize against hot L2.
// __launch_bounds__(256, 8) pins regs <= 32 so the tail cannot deflate
// occupancy (R8's failure mode: tail code pushed regs 40->56, occ to 46%).
__global__ __launch_bounds__(256, 8) void fused_kernel(
    const float4* __restrict__ pos4,
    const float4* __restrict__ lm4,
    const int4*   __restrict__ idx4,
    const float*  __restrict__ gf,     // (G, 256)
    const float*  __restrict__ Wv,     // (256,)
    const float*  __restrict__ bv,     // (1,)
    const float*  __restrict__ u,      // (G,)
    const float*  __restrict__ temp,   // scalar
    float*        __restrict__ out)    // (G, 5)
{
    const unsigned bidx  = blockIdx.x;
    const unsigned triad = bidx / 3u;
    const unsigned role  = bidx % 3u;

    if (role != 2u) {
        // ---- member scatter-reduce: 4 members per thread ----
        int t = (int)(triad * 2u + role) * blockDim.x + threadIdx.x;  // 0..M/4-1

        // Front-batch all 5 vector loads (idx, lm, 3x pos) for MLP.
        float4 lm = lm4[t];
        int4   ix = idx4[t];
        float4 p0 = pos4[3 * t + 0];
        float4 p1 = pos4[3 * t + 1];
        float4 p2 = pos4[3 * t + 2];

        float e0 = __expf(lm.x);
        float e1 = __expf(lm.y);
        float e2 = __expf(lm.z);
        float e3 = __expf(lm.w);

        // Per-warp replica choice spreads concurrent warps across replicas.
        float4* acc = g_acc[((bidx << 3) + (threadIdx.x >> 5)) & (R_REP - 1)];

        red_v4(&acc[ix.x], e0, e0 * p0.x, e0 * p0.y, e0 * p0.z);
        red_v4(&acc[ix.y], e1, e1 * p0.w, e1 * p1.x, e1 * p1.y);
        red_v4(&acc[ix.z], e2, e2 * p1.z, e2 * p1.w, e2 * p2.x);
        red_v4(&acc[ix.w], e3, e3 * p2.y, e3 * p2.z, e3 * p2.w);
    } else {
        // ---- warp-per-glimpse GEMV: 8 warps/block ----
        int gw   = (int)triad * 8 + (threadIdx.x >> 5);
        int lane = threadIdx.x & 31;
        if (gw < G_SEG) {
            const float4* row = (const float4*)(gf + (size_t)gw * D_FEAT);
            const float4* w4  = (const float4*)Wv;

            float s = 0.f;
#pragma unroll
            for (int k = 0; k < 2; k++) {
                float4 a = row[lane + 32 * k];
                float4 w = w4[lane + 32 * k];
                s += a.x * w.x + a.y * w.y + a.z * w.z + a.w * w.w;
            }
#pragma unroll
            for (int o = 16; o; o >>= 1) s += __shfl_xor_sync(0xFFFFFFFFu, s, o);

            if (lane == 0) {
                float logit = 8.8f * tanhf(s + bv[0]);
                float uu = u[gw];
                float relaxed = (logit + logf(uu) - log1pf(-uu)) / temp[0];
                float lzp = fminf(relaxed, 0.f) - log1pf(__expf(-fabsf(relaxed)));
                float* o5 = out + (size_t)gw * 5;
                o5[0] = lzp;
                o5[1] = logit;
            }
        }
    }

    // ---- completion rank: last FIN_BLOCKS finishers run the tail finalize ----
    __syncthreads();
    __shared__ unsigned int s_rank;
    if (threadIdx.x == 0) {
        __threadfence();                       // order this block's REDGs/stores
        s_rank = atomicAdd(&g_done, 1u);
    }
    __syncthreads();
    unsigned int rank = s_rank;
    if (rank < TOTAL_BLOCKS - FIN_BLOCKS) return;

    // Spin until every block has finished. Safe: only the last 64 finishers
    // spin, and every unfinished block is independent of them.
    if (threadIdx.x == 0) {
        while (*(volatile unsigned int*)&g_done < TOTAL_BLOCKS) { }
    }
    __syncthreads();
    __threadfence();                           // acquire all blocks' REDGs

    // Finalize slice: FIN_THREADS threads cover 20000 glimpses (hot L2 reads).
    int fidx = (int)(rank - (TOTAL_BLOCKS - FIN_BLOCKS)) * 256 + threadIdx.x;
    for (int g = fidx; g < G_SEG; g += FIN_THREADS) {
        float4 a = g_acc[0][g];
        float4 b = g_acc[1][g];
        g_acc[0][g] = make_float4(0.f, 0.f, 0.f, 0.f);   // clean for next replay
        g_acc[1][g] = make_float4(0.f, 0.f, 0.f, 0.f);

        float inv = 1.f / (a.x + b.x);
        float* o5 = out + (size_t)g * 5;
        o5[2] = (a.y + b.y) * inv;
        o5[3] = (a.z + b.z) * inv;
        o5[4] = (a.w + b.w) * inv;
    }

    // Last tail block resets counters for the next graph replay.
    __syncthreads();
    if (threadIdx.x == 0) {
        unsigned int old = atomicAdd(&g_fin, 1u);
        if (old == FIN_BLOCKS - 1) {
            g_fin  = 0u;
            g_done = 0u;                        // all spinners already exited
            __threadfence();
        }
    }
}

extern "C" void kernel_launch(void* const* d_in, const int* in_sizes, int n_in,
                              void* d_out, int out_size)
{
    const float* gf   = (const float*)d_in[0];   // glimpse_feature (G, 256)
    const float* pos  = (const float*)d_in[1];   // member_local_pos (M, 3)
    const float* lm   = (const float*)d_in[2];   // member_log_mask (M, 1)
    const int*   idx  = (const int*)  d_in[3];   // member_glimpse_index (M,)
    const float* u    = (const float*)d_in[4];   // u (G,)
    const float* Wv   = (const float*)d_in[5];   // W (256, 1)
    const float* bv   = (const float*)d_in[6];   // b (1,)
    const float* temp = (const float*)d_in[7];   // temperature scalar

    fused_kernel<<<TOTAL_BLOCKS, 256>>>(
        (const float4*)pos, (const float4*)lm, (const int4*)idx,
        gf, Wv, bv, u, temp, (float*)d_out);
}

// round 13
// speedup vs baseline: 1.0715x; 1.0715x over previous
#include <cuda_runtime.h>

#define G_SEG   20000
#define M_MEM   5120000
#define D_FEAT  256
#define R_REP   2

#define MEMBER_BLOCKS 5000            // (M/4)/256
#define GEMV_BLOCKS   2500            // 20000 warps / 8 warps per block
#define TOTAL_BLOCKS  (MEMBER_BLOCKS + GEMV_BLOCKS)

// Replicated per-glimpse accumulators: {sum_e, sum_e*px, sum_e*py, sum_e*pz}.
// 2 * 20000 * 16B = 640 KB, L2-resident. Zero-initialized at module load;
// finalize_kernel re-zeroes after reading, so every graph replay starts clean.
__device__ float4 g_acc[R_REP][G_SEG];

// One vectorized reduction per member: red.global.add.v4.f32 (sm_90+).
__device__ __forceinline__ void red_v4(float4* p, float a, float b, float c, float d) {
    asm volatile("red.global.add.v4.f32 [%0], {%1, %2, %3, %4};"
                 :: "l"(p), "f"(a), "f"(b), "f"(c), "f"(d)
                 : "memory");
}

// Fused kernel, 2:1 interleaved roles (R9 core — best measured):
//   blockIdx % 3 != 2 -> member scatter-reduce (4 members/thread)
//   blockIdx % 3 == 2 -> GEMV + presence logits (DRAM-streaming)
__global__ __launch_bounds__(256, 8) void fused_kernel(
    const float4* __restrict__ pos4,
    const float4* __restrict__ lm4,
    const int4*   __restrict__ idx4,
    const float*  __restrict__ gf,     // (G, 256)
    const float*  __restrict__ Wv,     // (256,)
    const float*  __restrict__ bv,     // (1,)
    const float*  __restrict__ u,      // (G,)
    const float*  __restrict__ temp,   // scalar
    float*        __restrict__ out)    // (G, 5)
{
    const unsigned bidx  = blockIdx.x;
    const unsigned triad = bidx / 3u;
    const unsigned role  = bidx % 3u;

    if (role != 2u) {
        // ---- member scatter-reduce: 4 members per thread ----
        int t = (int)(triad * 2u + role) * blockDim.x + threadIdx.x;  // 0..M/4-1

        // Front-batch all 5 vector loads (idx, lm, 3x pos) for MLP.
        float4 lm = lm4[t];
        int4   ix = idx4[t];
        float4 p0 = pos4[3 * t + 0];
        float4 p1 = pos4[3 * t + 1];
        float4 p2 = pos4[3 * t + 2];

        float e0 = __expf(lm.x);
        float e1 = __expf(lm.y);
        float e2 = __expf(lm.z);
        float e3 = __expf(lm.w);

        // Per-warp replica choice spreads concurrent warps across replicas.
        float4* acc = g_acc[((bidx << 3) + (threadIdx.x >> 5)) & (R_REP - 1)];

        red_v4(&acc[ix.x], e0, e0 * p0.x, e0 * p0.y, e0 * p0.z);
        red_v4(&acc[ix.y], e1, e1 * p0.w, e1 * p1.x, e1 * p1.y);
        red_v4(&acc[ix.z], e2, e2 * p1.z, e2 * p1.w, e2 * p2.x);
        red_v4(&acc[ix.w], e3, e3 * p2.y, e3 * p2.z, e3 * p2.w);
    } else {
        // ---- warp-per-glimpse GEMV: 8 warps/block ----
        int gw   = (int)triad * 8 + (threadIdx.x >> 5);
        int lane = threadIdx.x & 31;
        if (gw >= G_SEG) return;

        const float4* row = (const float4*)(gf + (size_t)gw * D_FEAT);
        const float4* w4  = (const float4*)Wv;

        float s = 0.f;
#pragma unroll
        for (int k = 0; k < 2; k++) {
            float4 a = row[lane + 32 * k];
            float4 w = w4[lane + 32 * k];
            s += a.x * w.x + a.y * w.y + a.z * w.z + a.w * w.w;
        }
#pragma unroll
        for (int o = 16; o; o >>= 1) s += __shfl_xor_sync(0xFFFFFFFFu, s, o);

        if (lane == 0) {
            float logit = 8.8f * tanhf(s + bv[0]);
            float uu = u[gw];
            float relaxed = (logit + logf(uu) - log1pf(-uu)) / temp[0];
            float lzp = fminf(relaxed, 0.f) - log1pf(__expf(-fabsf(relaxed)));
            float* o5 = out + (size_t)gw * 5;
            o5[0] = lzp;
            o5[1] = logit;
        }
    }
}

// Slim finalize with PDL: blocks are scheduled while fused_kernel drains;
// cudaGridDependencySynchronize() blocks until the primary's memory is
// visible, then reads hot-L2 accumulators. Re-zeroes for the next replay.
__global__ __launch_bounds__(128) void finalize_kernel(float* __restrict__ out)
{
#if __CUDA_ARCH__ >= 900
    cudaGridDependencySynchronize();
#endif
    int g = blockIdx.x * blockDim.x + threadIdx.x;
    if (g >= G_SEG) return;

    float4 a = g_acc[0][g];
    float4 b = g_acc[1][g];
    g_acc[0][g] = make_float4(0.f, 0.f, 0.f, 0.f);
    g_acc[1][g] = make_float4(0.f, 0.f, 0.f, 0.f);

    float inv = 1.f / (a.x + b.x);
    float* o5 = out + (size_t)g * 5;
    o5[2] = (a.y + b.y) * inv;
    o5[3] = (a.z + b.z) * inv;
    o5[4] = (a.w + b.w) * inv;
}

extern "C" void kernel_launch(void* const* d_in, const int* in_sizes, int n_in,
                              void* d_out, int out_size)
{
    const float* gf   = (const float*)d_in[0];   // glimpse_feature (G, 256)
    const float* pos  = (const float*)d_in[1];   // member_local_pos (M, 3)
    const float* lm   = (const float*)d_in[2];   // member_log_mask (M, 1)
    const int*   idx  = (const int*)  d_in[3];   // member_glimpse_index (M,)
    const float* u    = (const float*)d_in[4];   // u (G,)
    const float* Wv   = (const float*)d_in[5];   // W (256, 1)
    const float* bv   = (const float*)d_in[6];   // b (1,)
    const float* temp = (const float*)d_in[7];   // temperature scalar

    fused_kernel<<<TOTAL_BLOCKS, 256>>>(
        (const float4*)pos, (const float4*)lm, (const int4*)idx,
        gf, Wv, bv, u, temp, (float*)d_out);

    // PDL launch: overlap finalize's launch/scheduling latency with the
    // fused kernel's drain. Falls back to a plain launch on error.
    cudaLaunchConfig_t cfg = {};
    cfg.gridDim  = dim3((G_SEG + 127) / 128, 1, 1);
    cfg.blockDim = dim3(128, 1, 1);
    cudaLaunchAttribute attrs[1] = {};
    attrs[0].id = cudaLaunchAttributeProgrammaticStreamSerialization;
    attrs[0].val.programmaticStreamSerializationAllowed = 1;
    cfg.attrs    = attrs;
    cfg.numAttrs = 1;

    float* outp = (float*)d_out;
    cudaError_t err = cudaLaunchKernelEx(&cfg, finalize_kernel, outp);
    if (err != cudaSuccess) {
        finalize_kernel<<<(G_SEG + 127) / 128, 128>>>(outp);
    }
}

// round 14
// speedup vs baseline: 1.1022x; 1.0287x over previous
#include <cuda_runtime.h>

#define G_SEG   20000
#define M_MEM   5120000
#define D_FEAT  256
#define R_REP   2

#define MEMBER_BLOCKS 5000            // (M/4)/256
#define GEMV_BLOCKS   2500            // 20000 warps / 8 warps per block
#define TOTAL_BLOCKS  (MEMBER_BLOCKS + GEMV_BLOCKS)

// Replicated per-glimpse accumulators: {sum_e, sum_e*px, sum_e*py, sum_e*pz}.
// 2 * 20000 * 16B = 640 KB, L2-resident. Zero-initialized at module load;
// finalize_kernel re-zeroes after reading, so every graph replay starts clean.
__device__ float4 g_acc[R_REP][G_SEG];
// Presence results staged in L2 by the GEMV warps: {log_z_pres, logit_pres}.
__device__ float2 g_pres[G_SEG];

// One vectorized reduction per member: red.global.add.v4.f32 (sm_90+).
__device__ __forceinline__ void red_v4(float4* p, float a, float b, float c, float d) {
    asm volatile("red.global.add.v4.f32 [%0], {%1, %2, %3, %4};"
                 :: "l"(p), "f"(a), "f"(b), "f"(c), "f"(d)
                 : "memory");
}

// Fused kernel, 2:1 interleaved roles (R9 core — best measured fused ~39.6us,
// at the L1tex scatter-wavefront floor):
//   blockIdx % 3 != 2 -> member scatter-reduce (4 members/thread)
//   blockIdx % 3 == 2 -> GEMV + presence logits (staged to g_pres)
__global__ __launch_bounds__(256, 8) void fused_kernel(
    const float4* __restrict__ pos4,
    const float4* __restrict__ lm4,
    const int4*   __restrict__ idx4,
    const float*  __restrict__ gf,     // (G, 256)
    const float*  __restrict__ Wv,     // (256,)
    const float*  __restrict__ bv,     // (1,)
    const float*  __restrict__ u,      // (G,)
    const float*  __restrict__ temp)   // scalar
{
    const unsigned bidx  = blockIdx.x;
    const unsigned triad = bidx / 3u;
    const unsigned role  = bidx % 3u;

    if (role != 2u) {
        // ---- member scatter-reduce: 4 members per thread ----
        int t = (int)(triad * 2u + role) * blockDim.x + threadIdx.x;  // 0..M/4-1

        // Front-batch all 5 vector loads (idx, lm, 3x pos) for MLP.
        float4 lm = lm4[t];
        int4   ix = idx4[t];
        float4 p0 = pos4[3 * t + 0];
        float4 p1 = pos4[3 * t + 1];
        float4 p2 = pos4[3 * t + 2];

        float e0 = __expf(lm.x);
        float e1 = __expf(lm.y);
        float e2 = __expf(lm.z);
        float e3 = __expf(lm.w);

        // Per-warp replica choice spreads concurrent warps across replicas.
        float4* acc = g_acc[((bidx << 3) + (threadIdx.x >> 5)) & (R_REP - 1)];

        red_v4(&acc[ix.x], e0, e0 * p0.x, e0 * p0.y, e0 * p0.z);
        red_v4(&acc[ix.y], e1, e1 * p0.w, e1 * p1.x, e1 * p1.y);
        red_v4(&acc[ix.z], e2, e2 * p1.z, e2 * p1.w, e2 * p2.x);
        red_v4(&acc[ix.w], e3, e3 * p2.y, e3 * p2.z, e3 * p2.w);
    } else {
        // ---- warp-per-glimpse GEMV: 8 warps/block ----
        int gw   = (int)triad * 8 + (threadIdx.x >> 5);
        int lane = threadIdx.x & 31;
        if (gw >= G_SEG) return;

        const float4* row = (const float4*)(gf + (size_t)gw * D_FEAT);
        const float4* w4  = (const float4*)Wv;

        float s = 0.f;
#pragma unroll
        for (int k = 0; k < 2; k++) {
            float4 a = row[lane + 32 * k];
            float4 w = w4[lane + 32 * k];
            s += a.x * w.x + a.y * w.y + a.z * w.z + a.w * w.w;
        }
#pragma unroll
        for (int o = 16; o; o >>= 1) s += __shfl_xor_sync(0xFFFFFFFFu, s, o);

        if (lane == 0) {
            float logit = 8.8f * tanhf(s + bv[0]);
            float uu = u[gw];
            float relaxed = (logit + logf(uu) - log1pf(-uu)) / temp[0];
            float lzp = fminf(relaxed, 0.f) - log1pf(__expf(-fabsf(relaxed)));
            g_pres[gw] = make_float2(lzp, logit);   // L2 staging, 8B aligned
        }
    }
}

// Finalize: one thread per glimpse; reads hot-L2 g_acc + g_pres, zeroes
// g_acc for the next replay, stages full 5-float rows in smem (stride-5 ->
// bank-conflict-free), then block-copies to out as contiguous float4s
// (fully coalesced; 256 rows * 20B = 5120B per block, 16B-aligned).
__global__ __launch_bounds__(256) void finalize_kernel(float* __restrict__ out)
{
    __shared__ float srow[256 * 5];

    const int base = blockIdx.x * 256;
    const int g    = base + threadIdx.x;
    const int nrow = (G_SEG - base < 256) ? (G_SEG - base) : 256;

    if (g < G_SEG) {
        float4 a = g_acc[0][g];
        float4 b = g_acc[1][g];
        g_acc[0][g] = make_float4(0.f, 0.f, 0.f, 0.f);
        g_acc[1][g] = make_float4(0.f, 0.f, 0.f, 0.f);
        float2 pr = g_pres[g];

        float inv = 1.f / (a.x + b.x);
        float* r = srow + threadIdx.x * 5;
        r[0] = pr.x;
        r[1] = pr.y;
        r[2] = (a.y + b.y) * inv;
        r[3] = (a.z + b.z) * inv;
        r[4] = (a.w + b.w) * inv;
    }
    __syncthreads();

    // Contiguous vectorized copy: nrow*5 floats (multiple of 4 for both the
    // full block 1280 and the tail block 32*5=160).
    const int nf4 = (nrow * 5) >> 2;
    float4*       dst = (float4*)(out + (size_t)base * 5);
    const float4* src = (const float4*)srow;
    for (int i = threadIdx.x; i < nf4; i += 256) dst[i] = src[i];
}

extern "C" void kernel_launch(void* const* d_in, const int* in_sizes, int n_in,
                              void* d_out, int out_size)
{
    const float* gf   = (const float*)d_in[0];   // glimpse_feature (G, 256)
    const float* pos  = (const float*)d_in[1];   // member_local_pos (M, 3)
    const float* lm   = (const float*)d_in[2];   // member_log_mask (M, 1)
    const int*   idx  = (const int*)  d_in[3];   // member_glimpse_index (M,)
    const float* u    = (const float*)d_in[4];   // u (G,)
    const float* Wv   = (const float*)d_in[5];   // W (256, 1)
    const float* bv   = (const float*)d_in[6];   // b (1,)
    const float* temp = (const float*)d_in[7];   // temperature scalar

    fused_kernel<<<TOTAL_BLOCKS, 256>>>(
        (const float4*)pos, (const float4*)lm, (const int4*)idx,
        gf, Wv, bv, u, temp);

    finalize_kernel<<<(G_SEG + 255) / 256, 256>>>((float*)d_out);
}

// round 15
// speedup vs baseline: 1.1171x; 1.0135x over previous
#include <cuda_runtime.h>

#define G_SEG   20000
#define M_MEM   5120000
#define D_FEAT  256
#define R_REP   2

#define MEMBER_BLOCKS 5000            // (M/4)/256
#define GEMV_BLOCKS   2500            // 20000 warps / 8 warps per block
#define TOTAL_BLOCKS  (MEMBER_BLOCKS + GEMV_BLOCKS)

// Replicated per-glimpse accumulators: {sum_e, sum_e*px, sum_e*py, sum_e*pz}.
// 2 * 20000 * 16B = 640 KB, L2-resident. Zero-initialized at module load;
// finalize_kernel re-zeroes after reading, so every graph replay starts clean.
__device__ float4 g_acc[R_REP][G_SEG];

// One vectorized reduction per member: red.global.add.v4.f32 (sm_90+).
__device__ __forceinline__ void red_v4(float4* p, float a, float b, float c, float d) {
    asm volatile("red.global.add.v4.f32 [%0], {%1, %2, %3, %4};"
                 :: "l"(p), "f"(a), "f"(b), "f"(c), "f"(d)
                 : "memory");
}

// Fused kernel, 2:1 interleaved roles (R9 core — best measured fused time;
// member path sits at the L1tex scatter-wavefront floor ~40us):
//   blockIdx % 3 != 2 -> member scatter-reduce (4 members/thread)
//   blockIdx % 3 == 2 -> GEMV + presence logits (writes out cols 0-1)
__global__ __launch_bounds__(256, 8) void fused_kernel(
    const float4* __restrict__ pos4,
    const float4* __restrict__ lm4,
    const int4*   __restrict__ idx4,
    const float*  __restrict__ gf,     // (G, 256)
    const float*  __restrict__ Wv,     // (256,)
    const float*  __restrict__ bv,     // (1,)
    const float*  __restrict__ u,      // (G,)
    const float*  __restrict__ temp,   // scalar
    float*        __restrict__ out)    // (G, 5)
{
    const unsigned bidx  = blockIdx.x;
    const unsigned triad = bidx / 3u;
    const unsigned role  = bidx % 3u;

    if (role != 2u) {
        // ---- member scatter-reduce: 4 members per thread ----
        int t = (int)(triad * 2u + role) * blockDim.x + threadIdx.x;  // 0..M/4-1

        // Front-batch all 5 vector loads (idx, lm, 3x pos) for MLP.
        float4 lm = lm4[t];
        int4   ix = idx4[t];
        float4 p0 = pos4[3 * t + 0];
        float4 p1 = pos4[3 * t + 1];
        float4 p2 = pos4[3 * t + 2];

        float e0 = __expf(lm.x);
        float e1 = __expf(lm.y);
        float e2 = __expf(lm.z);
        float e3 = __expf(lm.w);

        // Per-warp replica choice spreads concurrent warps across replicas.
        float4* acc = g_acc[((bidx << 3) + (threadIdx.x >> 5)) & (R_REP - 1)];

        red_v4(&acc[ix.x], e0, e0 * p0.x, e0 * p0.y, e0 * p0.z);
        red_v4(&acc[ix.y], e1, e1 * p0.w, e1 * p1.x, e1 * p1.y);
        red_v4(&acc[ix.z], e2, e2 * p1.z, e2 * p1.w, e2 * p2.x);
        red_v4(&acc[ix.w], e3, e3 * p2.y, e3 * p2.z, e3 * p2.w);
    } else {
        // ---- warp-per-glimpse GEMV: 8 warps/block ----
        int gw   = (int)triad * 8 + (threadIdx.x >> 5);
        int lane = threadIdx.x & 31;
        if (gw >= G_SEG) return;

        const float4* row = (const float4*)(gf + (size_t)gw * D_FEAT);
        const float4* w4  = (const float4*)Wv;

        float s = 0.f;
#pragma unroll
        for (int k = 0; k < 2; k++) {
            float4 a = row[lane + 32 * k];
            float4 w = w4[lane + 32 * k];
            s += a.x * w.x + a.y * w.y + a.z * w.z + a.w * w.w;
        }
#pragma unroll
        for (int o = 16; o; o >>= 1) s += __shfl_xor_sync(0xFFFFFFFFu, s, o);

        if (lane == 0) {
            float logit = 8.8f * tanhf(s + bv[0]);
            float uu = u[gw];
            float relaxed = (logit + logf(uu) - log1pf(-uu)) / temp[0];
            float lzp = fminf(relaxed, 0.f) - log1pf(__expf(-fabsf(relaxed)));
            float* o5 = out + (size_t)gw * 5;
            o5[0] = lzp;
            o5[1] = logit;
        }
    }
}

// Finalize (R2 shape — fastest measured): 256-thread blocks, one glimpse per
// thread, direct loads/stores, no smem. Reads hot-L2 replicas, re-zeroes them
// for the next graph replay, writes center cols 2-4.
__global__ __launch_bounds__(256) void finalize_kernel(float* __restrict__ out)
{
    int g = blockIdx.x * blockDim.x + threadIdx.x;
    if (g >= G_SEG) return;

    float4 a = g_acc[0][g];
    float4 b = g_acc[1][g];
    g_acc[0][g] = make_float4(0.f, 0.f, 0.f, 0.f);
    g_acc[1][g] = make_float4(0.f, 0.f, 0.f, 0.f);

    float inv = 1.f / (a.x + b.x);
    float* o5 = out + (size_t)g * 5;
    o5[2] = (a.y + b.y) * inv;
    o5[3] = (a.z + b.z) * inv;
    o5[4] = (a.w + b.w) * inv;
}

extern "C" void kernel_launch(void* const* d_in, const int* in_sizes, int n_in,
                              void* d_out, int out_size)
{
    const float* gf   = (const float*)d_in[0];   // glimpse_feature (G, 256)
    const float* pos  = (const float*)d_in[1];   // member_local_pos (M, 3)
    const float* lm   = (const float*)d_in[2];   // member_log_mask (M, 1)
    const int*   idx  = (const int*)  d_in[3];   // member_glimpse_index (M,)
    const float* u    = (const float*)d_in[4];   // u (G,)
    const float* Wv   = (const float*)d_in[5];   // W (256, 1)
    const float* bv   = (const float*)d_in[6];   // b (1,)
    const float* temp = (const float*)d_in[7];   // temperature scalar

    fused_kernel<<<TOTAL_BLOCKS, 256>>>(
        (const float4*)pos, (const float4*)lm, (const int4*)idx,
        gf, Wv, bv, u, temp, (float*)d_out);

    finalize_kernel<<<(G_SEG + 255) / 256, 256>>>((float*)d_out);
}